// round 1
// baseline (speedup 1.0000x reference)
#include <cuda_runtime.h>
#include <cstdint>

// Problem constants (bin size is exactly 1.0 in both dims; XL=YL=0).
#define NUM_BINS_X 1024
#define NUM_BINS_Y 1024
#define NUM_NODES  4000000
#define NUM_FILLER 1000000
#define NUM_PHYS   (NUM_NODES - NUM_FILLER)   // 3,000,000
#define NUM_MOVABLE 2500000
#define SPAN 4

#define UNIT_PIN_CAPACITY 2.0f
#define MAX_ADJ 2.5f
#define MIN_ADJ (1.0f / 2.5f)
#define PIN_STRETCH_RATIO 1.414f

// 1024*1024 float bin map scratch (4 MB). Reused in place for adj.
__device__ float g_pmap[NUM_BINS_X * NUM_BINS_Y];

// ---------------------------------------------------------------------------
// Kernel 1: zero the bin map (float4 stores, 256K threads).
// ---------------------------------------------------------------------------
__global__ void zero_pmap_kernel() {
    int i = blockIdx.x * blockDim.x + threadIdx.x;
    float4* p = reinterpret_cast<float4*>(g_pmap);
    p[i] = make_float4(0.f, 0.f, 0.f, 0.f);
}

// ---------------------------------------------------------------------------
// Kernel 2: scatter pin density of physical nodes into bins.
// ---------------------------------------------------------------------------
__global__ void scatter_kernel(const float* __restrict__ pos,
                               const float* __restrict__ nsx,
                               const float* __restrict__ nsy,
                               const int*   __restrict__ pw) {
    int i = blockIdx.x * blockDim.x + threadIdx.x;
    if (i >= NUM_PHYS) return;

    float sx = nsx[i];
    float sy = nsy[i];
    float hx = 0.5f * fmaxf(PIN_STRETCH_RATIO, sx);   // bsx = 1.0
    float hy = 0.5f * fmaxf(PIN_STRETCH_RATIO, sy);
    float cx = pos[i]             + 0.5f * sx;
    float cy = pos[NUM_NODES + i] + 0.5f * sy;
    float xmin = cx - hx, xmax = cx + hx;
    float ymin = cy - hy, ymax = cy + hy;

    float dens = (float)pw[i] / (4.0f * hx * hy);

    int bxl = (int)floorf(xmin);
    int byl = (int)floorf(ymin);
    bxl = max(0, min(NUM_BINS_X - 1, bxl));
    byl = max(0, min(NUM_BINS_Y - 1, byl));

    #pragma unroll
    for (int di = 0; di < SPAN; ++di) {
        int bx = bxl + di;
        if (bx >= NUM_BINS_X) break;
        float bl = (float)bx;
        float ox = fminf(xmax, bl + 1.0f) - fmaxf(xmin, bl);
        if (ox <= 0.0f) break;            // overlap is monotone-decreasing past window
        float dox = dens * ox;
        #pragma unroll
        for (int dj = 0; dj < SPAN; ++dj) {
            int by = byl + dj;
            if (by >= NUM_BINS_Y) break;
            float blY = (float)by;
            float oy = fminf(ymax, blY + 1.0f) - fmaxf(ymin, blY);
            if (oy <= 0.0f) break;
            atomicAdd(&g_pmap[bx * NUM_BINS_Y + by], dox * oy);
        }
    }
}

// ---------------------------------------------------------------------------
// Kernel 3: pmap -> adj in place. adj = clip(pmap / CAP, MIN, MAX)  (bsx*bsy=1)
// ---------------------------------------------------------------------------
__global__ void adj_kernel() {
    int i = blockIdx.x * blockDim.x + threadIdx.x;
    float4* p = reinterpret_cast<float4*>(g_pmap);
    float4 v = p[i];
    v.x = fminf(fmaxf(v.x * (1.0f / UNIT_PIN_CAPACITY), MIN_ADJ), MAX_ADJ);
    v.y = fminf(fmaxf(v.y * (1.0f / UNIT_PIN_CAPACITY), MIN_ADJ), MAX_ADJ);
    v.z = fminf(fmaxf(v.z * (1.0f / UNIT_PIN_CAPACITY), MIN_ADJ), MAX_ADJ);
    v.w = fminf(fmaxf(v.w * (1.0f / UNIT_PIN_CAPACITY), MIN_ADJ), MAX_ADJ);
    p[i] = v;
}

// ---------------------------------------------------------------------------
// Kernel 4: gather adj-weighted overlap area per movable node.
// ---------------------------------------------------------------------------
__global__ void gather_kernel(const float* __restrict__ pos,
                              const float* __restrict__ nsx,
                              const float* __restrict__ nsy,
                              float* __restrict__ out) {
    int i = blockIdx.x * blockDim.x + threadIdx.x;
    if (i >= NUM_MOVABLE) return;

    float mx  = pos[i];
    float my  = pos[NUM_NODES + i];
    float msx = nsx[i];
    float msy = nsy[i];
    float xmax = mx + msx;
    float ymax = my + msy;

    int bxl = (int)floorf(mx);
    int byl = (int)floorf(my);
    bxl = max(0, min(NUM_BINS_X - 1, bxl));
    byl = max(0, min(NUM_BINS_Y - 1, byl));

    float area = 0.0f;
    #pragma unroll
    for (int di = 0; di < SPAN; ++di) {
        int bx = bxl + di;
        if (bx >= NUM_BINS_X) break;
        float bl = (float)bx;
        float ox = fminf(xmax, bl + 1.0f) - fmaxf(mx, bl);
        if (ox <= 0.0f) break;
        #pragma unroll
        for (int dj = 0; dj < SPAN; ++dj) {
            int by = byl + dj;
            if (by >= NUM_BINS_Y) break;
            float blY = (float)by;
            float oy = fminf(ymax, blY + 1.0f) - fmaxf(my, blY);
            if (oy <= 0.0f) break;
            area += ox * oy * g_pmap[bx * NUM_BINS_Y + by];
        }
    }
    out[i] = area;
}

// ---------------------------------------------------------------------------
extern "C" void kernel_launch(void* const* d_in, const int* in_sizes, int n_in,
                              void* d_out, int out_size) {
    const float* pos = (const float*)d_in[0];       // 8M floats (x then y)
    const float* nsx = (const float*)d_in[1];       // 4M
    const float* nsy = (const float*)d_in[2];       // 4M
    const int*   pw  = (const int*)  d_in[3];       // 3M int32
    float* out = (float*)d_out;                     // 2.5M floats

    const int T = 256;
    zero_pmap_kernel<<<(NUM_BINS_X * NUM_BINS_Y / 4) / T, T>>>();
    scatter_kernel<<<(NUM_PHYS + T - 1) / T, T>>>(pos, nsx, nsy, pw);
    adj_kernel<<<(NUM_BINS_X * NUM_BINS_Y / 4) / T, T>>>();
    gather_kernel<<<(NUM_MOVABLE + T - 1) / T, T>>>(pos, nsx, nsy, out);
}

// round 4
// speedup vs baseline: 1.2985x; 1.2985x over previous
#include <cuda_runtime.h>
#include <cstdint>

// Problem constants (bin size is exactly 1.0 in both dims; XL=YL=0).
#define NUM_BINS_X 1024
#define NUM_BINS_Y 1024
#define NUM_NODES  4000000
#define NUM_FILLER 1000000
#define NUM_PHYS   (NUM_NODES - NUM_FILLER)   // 3,000,000
#define NUM_MOVABLE 2500000

#define UNIT_PIN_CAPACITY 2.0f
#define MAX_ADJ 2.5f
#define MIN_ADJ (1.0f / 2.5f)
#define PIN_STRETCH_RATIO 1.414f

// Bin map scratch (4 MB) + 16-float pad: v2 REDs / float2 loads with an
// 8B-aligned base (byl & ~1) can index up to pmap_size+2; padded slots only
// ever receive exact 0.0f adds and are multiplied by 0.0f on the read side.
#define PMAP_N   (NUM_BINS_X * NUM_BINS_Y)
#define PMAP_PAD 16
__device__ __align__(16) float g_pmap[PMAP_N + PMAP_PAD];

// ---------------------------------------------------------------------------
// Kernel 1: zero the bin map incl. pad (float4 stores).
// ---------------------------------------------------------------------------
__global__ void zero_pmap_kernel() {
    int i = blockIdx.x * blockDim.x + threadIdx.x;
    if (i < (PMAP_N + PMAP_PAD) / 4) {
        reinterpret_cast<float4*>(g_pmap)[i] = make_float4(0.f, 0.f, 0.f, 0.f);
    }
}

__device__ __forceinline__ void red_v2(float* addr, float v0, float v1) {
    asm volatile("red.global.add.v2.f32 [%0], {%1, %2};"
                 :: "l"(addr), "f"(v0), "f"(v1) : "memory");
}

// ---------------------------------------------------------------------------
// Kernel 2: scatter pin density into bins with vectorized f32x2 reductions.
// Window is provably <= 3x3 bins (width < 2.0, bin size 1.0). The 3 y-bins
// byl..byl+2 are covered by two 8B-aligned f32x2 REDs at base b0 = byl & ~1.
// Slots outside the window contribute exactly 0.0f (matches reference's
// clip/where-masked scatter numerics).
// ---------------------------------------------------------------------------
__global__ void __launch_bounds__(256) scatter_kernel(
        const float* __restrict__ pos,
        const float* __restrict__ nsx,
        const float* __restrict__ nsy,
        const int*   __restrict__ pw) {
    int i = blockIdx.x * blockDim.x + threadIdx.x;
    if (i >= NUM_PHYS) return;

    float sx = nsx[i];
    float sy = nsy[i];
    float hx = 0.5f * fmaxf(PIN_STRETCH_RATIO, sx);   // bsx = 1.0
    float hy = 0.5f * fmaxf(PIN_STRETCH_RATIO, sy);
    float cx = pos[i]             + 0.5f * sx;
    float cy = pos[NUM_NODES + i] + 0.5f * sy;
    float xmin = cx - hx, xmax = cx + hx;
    float ymin = cy - hy, ymax = cy + hy;

    float dens = (float)pw[i] / (4.0f * hx * hy);

    int bxl = max(0, min(NUM_BINS_X - 1, (int)floorf(xmin)));
    int byl = max(0, min(NUM_BINS_Y - 1, (int)floorf(ymin)));
    int b0  = byl & ~1;                                // 8B-aligned y base

    // y overlaps for the 4 slots b0..b0+3 (clipped to >= 0).
    float oy0 = fmaxf(fminf(ymax, (float)(b0 + 1)) - fmaxf(ymin, (float)(b0 + 0)), 0.0f);
    float oy1 = fmaxf(fminf(ymax, (float)(b0 + 2)) - fmaxf(ymin, (float)(b0 + 1)), 0.0f);
    float oy2 = fmaxf(fminf(ymax, (float)(b0 + 3)) - fmaxf(ymin, (float)(b0 + 2)), 0.0f);
    float oy3 = fmaxf(fminf(ymax, (float)(b0 + 4)) - fmaxf(ymin, (float)(b0 + 3)), 0.0f);

    #pragma unroll
    for (int di = 0; di < 3; ++di) {
        int bx = bxl + di;
        float bl = (float)bx;
        float ox = fminf(xmax, bl + 1.0f) - fmaxf(xmin, bl);
        if (ox <= 0.0f) continue;                      // bx>=1024 also lands here
        float d = dens * ox;
        float* base = g_pmap + bx * NUM_BINS_Y + b0;
        float v0 = d * oy0, v1 = d * oy1, v2 = d * oy2, v3 = d * oy3;
        if (v0 + v1 > 0.0f) red_v2(base,     v0, v1);
        if (v2 + v3 > 0.0f) red_v2(base + 2, v2, v3);
    }
}

// ---------------------------------------------------------------------------
// Kernel 3: gather adj-weighted overlap per movable node (adj fused in).
// Straight-line 3x3: all 6 float2 loads issued up front for max MLP.
// ---------------------------------------------------------------------------
__device__ __forceinline__ float adj_of(float v) {
    return fminf(fmaxf(v * (1.0f / UNIT_PIN_CAPACITY), MIN_ADJ), MAX_ADJ);
}

__global__ void __launch_bounds__(256) gather_kernel(
        const float* __restrict__ pos,
        const float* __restrict__ nsx,
        const float* __restrict__ nsy,
        float* __restrict__ out) {
    int i = blockIdx.x * blockDim.x + threadIdx.x;
    if (i >= NUM_MOVABLE) return;

    float mx  = pos[i];
    float my  = pos[NUM_NODES + i];
    float xmax = mx + nsx[i];
    float ymax = my + nsy[i];

    int bxl = max(0, min(NUM_BINS_X - 1, (int)floorf(mx)));
    int byl = max(0, min(NUM_BINS_Y - 1, (int)floorf(my)));
    int b0  = byl & ~1;

    float oy0 = fmaxf(fminf(ymax, (float)(b0 + 1)) - fmaxf(my, (float)(b0 + 0)), 0.0f);
    float oy1 = fmaxf(fminf(ymax, (float)(b0 + 2)) - fmaxf(my, (float)(b0 + 1)), 0.0f);
    float oy2 = fmaxf(fminf(ymax, (float)(b0 + 3)) - fmaxf(my, (float)(b0 + 2)), 0.0f);
    float oy3 = fmaxf(fminf(ymax, (float)(b0 + 4)) - fmaxf(my, (float)(b0 + 3)), 0.0f);

    float ox[3];
    const float2* pa[3];
    const float2* pb[3];
    #pragma unroll
    for (int di = 0; di < 3; ++di) {
        int bx = bxl + di;
        float bl = (float)bx;
        ox[di] = fmaxf(fminf(xmax, bl + 1.0f) - fmaxf(mx, bl), 0.0f);
        int row = min(bx, NUM_BINS_X - 1) * NUM_BINS_Y;  // ox==0 masks clamped rows
        pa[di] = reinterpret_cast<const float2*>(g_pmap + row + b0);
        pb[di] = reinterpret_cast<const float2*>(g_pmap + row + b0 + 2);
    }

    // Issue all 6 loads back-to-back (independent -> MLP 6).
    float2 a0 = __ldg(pa[0]); float2 b0v = __ldg(pb[0]);
    float2 a1 = __ldg(pa[1]); float2 b1v = __ldg(pb[1]);
    float2 a2 = __ldg(pa[2]); float2 b2v = __ldg(pb[2]);

    float s0 = oy0 * adj_of(a0.x) + oy1 * adj_of(a0.y)
             + oy2 * adj_of(b0v.x) + oy3 * adj_of(b0v.y);
    float s1 = oy0 * adj_of(a1.x) + oy1 * adj_of(a1.y)
             + oy2 * adj_of(b1v.x) + oy3 * adj_of(b1v.y);
    float s2 = oy0 * adj_of(a2.x) + oy1 * adj_of(a2.y)
             + oy2 * adj_of(b2v.x) + oy3 * adj_of(b2v.y);

    out[i] = ox[0] * s0 + ox[1] * s1 + ox[2] * s2;
}

// ---------------------------------------------------------------------------
extern "C" void kernel_launch(void* const* d_in, const int* in_sizes, int n_in,
                              void* d_out, int out_size) {
    const float* pos = (const float*)d_in[0];       // 8M floats (x then y)
    const float* nsx = (const float*)d_in[1];       // 4M
    const float* nsy = (const float*)d_in[2];       // 4M
    const int*   pw  = (const int*)  d_in[3];       // 3M int32
    float* out = (float*)d_out;                     // 2.5M floats

    const int T = 256;
    zero_pmap_kernel<<<((PMAP_N + PMAP_PAD) / 4 + T - 1) / T, T>>>();
    scatter_kernel<<<(NUM_PHYS + T - 1) / T, T>>>(pos, nsx, nsy, pw);
    gather_kernel<<<(NUM_MOVABLE + T - 1) / T, T>>>(pos, nsx, nsy, out);
}

// round 5
// speedup vs baseline: 1.5280x; 1.1767x over previous
#include <cuda_runtime.h>
#include <cstdint>

// Problem constants (bin size is exactly 1.0 in both dims; XL=YL=0).
#define NUM_BINS_X 1024
#define NUM_BINS_Y 1024
#define NUM_NODES  4000000
#define NUM_FILLER 1000000
#define NUM_PHYS   (NUM_NODES - NUM_FILLER)   // 3,000,000
#define NUM_MOVABLE 2500000

#define UNIT_PIN_CAPACITY 2.0f
#define MAX_ADJ 2.5f
#define MIN_ADJ (1.0f / 2.5f)
#define PIN_STRETCH_RATIO 1.414f

// Bin map scratch (4 MB) + 16-float pad: v2/v4 REDs and float2/float4 loads
// with an 8B-aligned base (byl & ~1) can index up to pmap_size+2; padded
// slots only ever receive exact 0.0f adds and are multiplied by 0.0f reads.
#define PMAP_N   (NUM_BINS_X * NUM_BINS_Y)
#define PMAP_PAD 16
__device__ __align__(16) float g_pmap[PMAP_N + PMAP_PAD];

__device__ __forceinline__ void red_v2(float* addr, float v0, float v1) {
    asm volatile("red.global.add.v2.f32 [%0], {%1, %2};"
                 :: "l"(addr), "f"(v0), "f"(v1) : "memory");
}
__device__ __forceinline__ void red_v4(float* addr, float v0, float v1,
                                       float v2, float v3) {
    asm volatile("red.global.add.v4.f32 [%0], {%1, %2, %3, %4};"
                 :: "l"(addr), "f"(v0), "f"(v1), "f"(v2), "f"(v3) : "memory");
}

// ---------------------------------------------------------------------------
// Kernel 1: scatter pin density into bins with vectorized f32 reductions.
// Window is provably <= 3x3 bins (node width < 2.0, bin size 1.0). The 3
// y-bins byl..byl+2 live in the 4 slots at b0 = byl & ~1. When b0 is 16B
// aligned (byl % 4 <= 1) a single v4 RED covers them; otherwise two v2 REDs.
// Out-of-window slots contribute exactly 0.0f (matches reference masking).
// ---------------------------------------------------------------------------
__global__ void __launch_bounds__(256) scatter_kernel(
        const float* __restrict__ pos,
        const float* __restrict__ nsx,
        const float* __restrict__ nsy,
        const int*   __restrict__ pw) {
    int i = blockIdx.x * blockDim.x + threadIdx.x;
    if (i >= NUM_PHYS) return;

    float sx = nsx[i];
    float sy = nsy[i];
    float hx = 0.5f * fmaxf(PIN_STRETCH_RATIO, sx);   // bsx = 1.0
    float hy = 0.5f * fmaxf(PIN_STRETCH_RATIO, sy);
    float cx = pos[i]             + 0.5f * sx;
    float cy = pos[NUM_NODES + i] + 0.5f * sy;
    float xmin = cx - hx, xmax = cx + hx;
    float ymin = cy - hy, ymax = cy + hy;

    float dens = (float)pw[i] / (4.0f * hx * hy);

    int bxl = max(0, min(NUM_BINS_X - 1, (int)floorf(xmin)));
    int byl = max(0, min(NUM_BINS_Y - 1, (int)floorf(ymin)));
    int b0  = byl & ~1;                                // 8B-aligned y base
    bool aligned4 = ((b0 & 3) == 0);                   // 16B-aligned group

    // y overlaps for the 4 slots b0..b0+3 (clipped to >= 0).
    float oy0 = fmaxf(fminf(ymax, (float)(b0 + 1)) - fmaxf(ymin, (float)(b0 + 0)), 0.0f);
    float oy1 = fmaxf(fminf(ymax, (float)(b0 + 2)) - fmaxf(ymin, (float)(b0 + 1)), 0.0f);
    float oy2 = fmaxf(fminf(ymax, (float)(b0 + 3)) - fmaxf(ymin, (float)(b0 + 2)), 0.0f);
    float oy3 = fmaxf(fminf(ymax, (float)(b0 + 4)) - fmaxf(ymin, (float)(b0 + 3)), 0.0f);
    bool pair2 = (oy2 + oy3) > 0.0f;

    #pragma unroll
    for (int di = 0; di < 3; ++di) {
        int bx = bxl + di;
        float bl = (float)bx;
        float ox = fminf(xmax, bl + 1.0f) - fmaxf(xmin, bl);
        if (ox <= 0.0f) continue;                      // bx>=1024 also lands here
        float d = dens * ox;
        float* base = g_pmap + bx * NUM_BINS_Y + b0;
        float v0 = d * oy0, v1 = d * oy1, v2 = d * oy2, v3 = d * oy3;
        if (aligned4) {
            red_v4(base, v0, v1, v2, v3);              // one LTS op / column
        } else {
            red_v2(base, v0, v1);                      // slot byl always nonzero
            if (pair2) red_v2(base + 2, v2, v3);
        }
    }
}

// ---------------------------------------------------------------------------
// Kernel 2: gather adj-weighted overlap per movable node (adj fused in).
// Straight-line 3x3; per-row 4-slot group loaded as one float4 when 16B
// aligned, else two float2. All loads issued up front for max MLP.
// ---------------------------------------------------------------------------
__device__ __forceinline__ float adj_of(float v) {
    return fminf(fmaxf(v * (1.0f / UNIT_PIN_CAPACITY), MIN_ADJ), MAX_ADJ);
}

__global__ void __launch_bounds__(256) gather_kernel(
        const float* __restrict__ pos,
        const float* __restrict__ nsx,
        const float* __restrict__ nsy,
        float* __restrict__ out) {
    int i = blockIdx.x * blockDim.x + threadIdx.x;
    if (i >= NUM_MOVABLE) return;

    float mx  = pos[i];
    float my  = pos[NUM_NODES + i];
    float xmax = mx + nsx[i];
    float ymax = my + nsy[i];

    int bxl = max(0, min(NUM_BINS_X - 1, (int)floorf(mx)));
    int byl = max(0, min(NUM_BINS_Y - 1, (int)floorf(my)));
    int b0  = byl & ~1;

    float oy0 = fmaxf(fminf(ymax, (float)(b0 + 1)) - fmaxf(my, (float)(b0 + 0)), 0.0f);
    float oy1 = fmaxf(fminf(ymax, (float)(b0 + 2)) - fmaxf(my, (float)(b0 + 1)), 0.0f);
    float oy2 = fmaxf(fminf(ymax, (float)(b0 + 3)) - fmaxf(my, (float)(b0 + 2)), 0.0f);
    float oy3 = fmaxf(fminf(ymax, (float)(b0 + 4)) - fmaxf(my, (float)(b0 + 3)), 0.0f);

    float ox[3];
    const float* rp[3];
    #pragma unroll
    for (int di = 0; di < 3; ++di) {
        int bx = bxl + di;
        float bl = (float)bx;
        ox[di] = fmaxf(fminf(xmax, bl + 1.0f) - fmaxf(mx, bl), 0.0f);
        int row = min(bx, NUM_BINS_X - 1) * NUM_BINS_Y;  // ox==0 masks clamped rows
        rp[di] = g_pmap + row + b0;
    }

    float4 q0, q1, q2;
    if ((b0 & 3) == 0) {
        // One 16B load per row (3 LTS requests total).
        q0 = __ldg(reinterpret_cast<const float4*>(rp[0]));
        q1 = __ldg(reinterpret_cast<const float4*>(rp[1]));
        q2 = __ldg(reinterpret_cast<const float4*>(rp[2]));
    } else {
        float2 a0 = __ldg(reinterpret_cast<const float2*>(rp[0]));
        float2 a1 = __ldg(reinterpret_cast<const float2*>(rp[1]));
        float2 a2 = __ldg(reinterpret_cast<const float2*>(rp[2]));
        float2 c0 = __ldg(reinterpret_cast<const float2*>(rp[0] + 2));
        float2 c1 = __ldg(reinterpret_cast<const float2*>(rp[1] + 2));
        float2 c2 = __ldg(reinterpret_cast<const float2*>(rp[2] + 2));
        q0 = make_float4(a0.x, a0.y, c0.x, c0.y);
        q1 = make_float4(a1.x, a1.y, c1.x, c1.y);
        q2 = make_float4(a2.x, a2.y, c2.x, c2.y);
    }

    float s0 = oy0 * adj_of(q0.x) + oy1 * adj_of(q0.y)
             + oy2 * adj_of(q0.z) + oy3 * adj_of(q0.w);
    float s1 = oy0 * adj_of(q1.x) + oy1 * adj_of(q1.y)
             + oy2 * adj_of(q1.z) + oy3 * adj_of(q1.w);
    float s2 = oy0 * adj_of(q2.x) + oy1 * adj_of(q2.y)
             + oy2 * adj_of(q2.z) + oy3 * adj_of(q2.w);

    out[i] = ox[0] * s0 + ox[1] * s1 + ox[2] * s2;
}

// ---------------------------------------------------------------------------
extern "C" void kernel_launch(void* const* d_in, const int* in_sizes, int n_in,
                              void* d_out, int out_size) {
    const float* pos = (const float*)d_in[0];       // 8M floats (x then y)
    const float* nsx = (const float*)d_in[1];       // 4M
    const float* nsy = (const float*)d_in[2];       // 4M
    const int*   pw  = (const int*)  d_in[3];       // 3M int32
    float* out = (float*)d_out;                     // 2.5M floats

    // Zero the bin map via a memset node (full-BW fill, ~1us).
    void* pmap_ptr = nullptr;
    cudaGetSymbolAddress(&pmap_ptr, g_pmap);
    cudaMemsetAsync(pmap_ptr, 0, (PMAP_N + PMAP_PAD) * sizeof(float));

    const int T = 256;
    scatter_kernel<<<(NUM_PHYS + T - 1) / T, T>>>(pos, nsx, nsy, pw);
    gather_kernel<<<(NUM_MOVABLE + T - 1) / T, T>>>(pos, nsx, nsy, out);
}